// round 8
// baseline (speedup 1.0000x reference)
#include <cuda_runtime.h>
#include <math.h>
#include <stdint.h>

#define B_  32
#define S1_ 128
#define T_  50
#define E_  768
#define H_  1024
#define V_  32000

// ---------------- device scratch (no allocation allowed) ----------------
__device__ float g_xW[B_ * S1_ * H_];     // x @ W1x^T  (precomputed once)
__device__ float g_hW[B_ * H_];           // h2 @ W1h^T + b1 (per step)
__device__ float g_scores[B_ * S1_];
__device__ float g_inp0[B_ * 2 * E_];     // [emb_t ; context]
__device__ float g_h[3 * B_ * H_];
__device__ float g_c[3 * B_ * H_];
__device__ float g_gates[B_ * 4 * H_];
__device__ float g_bsum[3 * 4 * H_];      // bih + bhh per layer

// ---------------- f32x2 packed helpers ----------------
__device__ __forceinline__ unsigned long long ffma2_(unsigned long long a,
                                                     unsigned long long b,
                                                     unsigned long long c) {
    unsigned long long d;
    asm("fma.rn.f32x2 %0, %1, %2, %3;" : "=l"(d) : "l"(a), "l"(b), "l"(c));
    return d;
}
__device__ __forceinline__ unsigned long long bcast2_(float x) {
    unsigned long long r;
    asm("mov.b64 %0, {%1, %1};" : "=l"(r) : "f"(x));
    return r;
}
__device__ __forceinline__ void unpack2_(unsigned long long v, float& lo, float& hi) {
    asm("mov.b64 {%0, %1}, %2;" : "=f"(lo), "=f"(hi) : "l"(v));
}
// TF32 operand rounding (matches cublas TF32 path: cvt.rna)
__device__ __forceinline__ float tf32r(float x) {
    unsigned u;
    asm("cvt.rna.tf32.f32 %0, %1;" : "=r"(u) : "f"(x));
    return __uint_as_float(u);
}

// ---------------- M=32 specialized GEMM (TF32-operand, fp32 accumulate):
// out[m,n] = sum_k tf32(inp[m,k]) * tf32(W[n,k]) + bias[n]
// Optional second (inp,W) pair accumulated into the same output.
// 128 threads. NT columns per block; thread covers NT/4 m's as f32x2 pairs.
// K must be a multiple of 32, N a multiple of NT. grid.y tiles M in chunks of 32.
template <int NT>
__global__ void __launch_bounds__(128) gemm32(
    const float* __restrict__ inpA, int ldA, const float* __restrict__ WA, int ldWA, int KA,
    const float* __restrict__ inpB, int ldB, const float* __restrict__ WB, int ldWB, int KB,
    const float* __restrict__ bias, float* __restrict__ out, long long ldOut)
{
    constexpr int MPT = NT / 4;   // m values per thread
    constexpr int RM2 = NT / 8;   // f32x2 accumulators per thread
    __shared__ float sh[32 * 36];

    const int tid   = threadIdx.x;
    const int n     = blockIdx.x * NT + (tid % NT);
    const int m0    = (tid / NT) * MPT;
    const int mbase = blockIdx.y * 32;

    unsigned long long acc[RM2];
#pragma unroll
    for (int r = 0; r < RM2; r++) acc[r] = 0ull;

    const float* inP = inpA; int ldI = ldA; const float* Wp = WA; int ldW = ldWA; int K = KA;
    for (int seg = 0; seg < 2; seg++) {
        if (seg == 1) {
            if (!inpB) break;
            inP = inpB; ldI = ldB; Wp = WB; ldW = ldWB; K = KB;
        }
        const float* wrow = Wp + (size_t)n * ldW;
        for (int k0 = 0; k0 < K; k0 += 32) {
            __syncthreads();
            {
                const int lane = tid & 31;
                const int mq   = tid >> 5;
#pragma unroll
                for (int i = 0; i < 8; i++) {
                    int m = i * 4 + mq;
                    sh[lane * 36 + m] = tf32r(inP[(size_t)(mbase + m) * ldI + k0 + lane]);
                }
            }
            __syncthreads();
#pragma unroll
            for (int kk = 0; kk < 32; kk += 4) {
                const float4 w4 = *reinterpret_cast<const float4*>(wrow + k0 + kk);
#pragma unroll
                for (int j = 0; j < 4; j++) {
                    float wj = (j == 0) ? w4.x : (j == 1) ? w4.y : (j == 2) ? w4.z : w4.w;
                    const unsigned long long wd = bcast2_(tf32r(wj));
#pragma unroll
                    for (int g = 0; g < RM2 / 2; g++) {
                        const ulonglong2 a = *reinterpret_cast<const ulonglong2*>(
                            &sh[(kk + j) * 36 + m0 + g * 4]);
                        acc[2 * g]     = ffma2_(a.x, wd, acc[2 * g]);
                        acc[2 * g + 1] = ffma2_(a.y, wd, acc[2 * g + 1]);
                    }
                }
            }
        }
    }

    const float bv = bias ? bias[n] : 0.f;
#pragma unroll
    for (int r = 0; r < RM2; r++) {
        float lo, hi;
        unpack2_(acc[r], lo, hi);
        const int m = m0 + 2 * r;
        out[(size_t)(mbase + m) * ldOut + n]     = lo + bv;
        out[(size_t)(mbase + m + 1) * ldOut + n] = hi + bv;
    }
}

// ---------------- attention: scores[b,s] = sum_h relu(xW + hW) * w2 + b2 ----------------
__global__ void __launch_bounds__(128) attn_scores(const float* __restrict__ w2,
                                                   const float* __restrict__ b2p)
{
    const int s = blockIdx.x, b = blockIdx.y, tid = threadIdx.x;
    const float* xw = g_xW + (size_t)(b * S1_ + s) * H_;
    const float* hw = g_hW + b * H_;
    float p = 0.f;
    for (int h = tid; h < H_; h += 128) {
        float v = xw[h] + hw[h];          // b1 already folded into hW
        v = fmaxf(v, 0.f);
        p += v * w2[h];
    }
    __shared__ float red[128];
    red[tid] = p; __syncthreads();
    for (int st = 64; st > 0; st >>= 1) {
        if (tid < st) red[tid] += red[tid + st];
        __syncthreads();
    }
    if (tid == 0) g_scores[b * S1_ + s] = red[0] + b2p[0];
}

// ---------------- attention: log_softmax(scores) -> context; also build inp0 ----------------
__global__ void __launch_bounds__(128) attn_context(const float* __restrict__ x,
                                                    const int* __restrict__ tseq,
                                                    const float* __restrict__ emb,
                                                    int t)
{
    const int c = blockIdx.x, b = blockIdx.y, tid = threadIdx.x;
    __shared__ float sc[128];
    __shared__ float red[128];

    const float s0 = g_scores[b * S1_ + tid];
    red[tid] = s0;
    __syncthreads();
    for (int st = 64; st > 0; st >>= 1) {
        if (tid < st) red[tid] = fmaxf(red[tid], red[tid + st]);
        __syncthreads();
    }
    const float mx = red[0];
    __syncthreads();
    const float sh = s0 - mx;             // shifted (JAX log_softmax form)
    red[tid] = expf(sh);
    __syncthreads();
    for (int st = 64; st > 0; st >>= 1) {
        if (tid < st) red[tid] += red[tid + st];
        __syncthreads();
    }
    const float lse = logf(red[0]);
    __syncthreads();
    sc[tid] = sh - lse;                   // logw
    __syncthreads();

    const int e = c * 128 + tid;          // e in [0,768)
    const float* xb = x + (size_t)b * S1_ * E_ + e;
    float ctx = 0.f;
#pragma unroll 4
    for (int s = 0; s < S1_; s++) ctx += sc[s] * xb[(size_t)s * E_];
    g_inp0[b * 2 * E_ + E_ + e] = ctx;

    const int tgt = tseq[b * T_ + t];
    g_inp0[b * 2 * E_ + e] = emb[(size_t)tgt * E_ + e];
}

// ---------------- LSTM pointwise update (gates already include biases) ----------------
__global__ void __launch_bounds__(1024) lstm_pointwise(int l)
{
    const int b = blockIdx.x, j = threadIdx.x;
    const float* gr = g_gates + b * 4 * H_;
    const float gi = gr[j];
    const float gf = gr[H_ + j];
    const float gg = gr[2 * H_ + j];
    const float go = gr[3 * H_ + j];
    float* cp = g_c + (size_t)(l * B_ + b) * H_ + j;
    float* hp = g_h + (size_t)(l * B_ + b) * H_ + j;
    const float si = 1.f / (1.f + expf(-gi));
    const float sf = 1.f / (1.f + expf(-gf));
    const float so = 1.f / (1.f + expf(-go));
    const float cn = sf * (*cp) + si * tanhf(gg);
    *cp = cn;
    *hp = so * tanhf(cn);
}

// ---------------- in-place log_softmax over V per batch row ----------------
__global__ void __launch_bounds__(1024) logsoftmax_v(float* __restrict__ out, long long ldOut)
{
    const int b = blockIdx.x, tid = threadIdx.x;
    float* row = out + (size_t)b * ldOut;
    __shared__ float red[1024];

    float m = -1e30f;
    for (int v = tid; v < V_; v += 1024) m = fmaxf(m, row[v]);
    red[tid] = m; __syncthreads();
    for (int st = 512; st > 0; st >>= 1) {
        if (tid < st) red[tid] = fmaxf(red[tid], red[tid + st]);
        __syncthreads();
    }
    m = red[0];
    __syncthreads();

    float s = 0.f;
    for (int v = tid; v < V_; v += 1024) s += expf(row[v] - m);
    red[tid] = s; __syncthreads();
    for (int st = 512; st > 0; st >>= 1) {
        if (tid < st) red[tid] += red[tid + st];
        __syncthreads();
    }
    const float lse = logf(red[0]);

    for (int v = tid; v < V_; v += 1024) row[v] = (row[v] - m) - lse;
}

// ---------------- init kernels ----------------
__global__ void zero_state()
{
    const int idx = blockIdx.x * 1024 + threadIdx.x;
    if (idx < 3 * B_ * H_) { g_h[idx] = 0.f; g_c[idx] = 0.f; }
}
__global__ void bias_sum(const float* bi0, const float* bh0,
                         const float* bi1, const float* bh1,
                         const float* bi2, const float* bh2)
{
    const int i = blockIdx.x * 1024 + threadIdx.x;
    if (i < 4 * H_) {
        g_bsum[i]            = bi0[i] + bh0[i];
        g_bsum[4 * H_ + i]   = bi1[i] + bh1[i];
        g_bsum[8 * H_ + i]   = bi2[i] + bh2[i];
    }
}

// ---------------- launch ----------------
extern "C" void kernel_launch(void* const* d_in, const int* in_sizes, int n_in,
                              void* d_out, int out_size)
{
    const float* x    = (const float*)d_in[0];
    const int*   tseq = (const int*)  d_in[1];
    const float* emb  = (const float*)d_in[2];
    const float* W1   = (const float*)d_in[3];   // (H, E+H)
    const float* b1   = (const float*)d_in[4];
    const float* W2   = (const float*)d_in[5];   // (1, H)
    const float* b2   = (const float*)d_in[6];

    // Input ordering: setup_inputs() dict order puts fc_W, fc_b at [7],[8]
    // BEFORE the LSTM weights ([9..20]). Detect by size for safety:
    // fc_W has V*H = 32,768,000 elements; Wih0 has 4H*2E = 6,291,456.
    const float *fcW, *fcb;
    const float *Wih[3], *Whh[3], *bih[3], *bhh[3];
    int base;
    if (in_sizes[7] == V_ * H_) {          // dict order (expected)
        fcW = (const float*)d_in[7];
        fcb = (const float*)d_in[8];
        base = 9;
    } else {                                // signature order (fallback)
        fcW = (const float*)d_in[19];
        fcb = (const float*)d_in[20];
        base = 7;
    }
    for (int l = 0; l < 3; l++) {
        Wih[l] = (const float*)d_in[base + 4 * l + 0];
        Whh[l] = (const float*)d_in[base + 4 * l + 1];
        bih[l] = (const float*)d_in[base + 4 * l + 2];
        bhh[l] = (const float*)d_in[base + 4 * l + 3];
    }
    float* out = (float*)d_out;

    float *xW, *hW, *inp0, *h, *gates, *bsum;
    cudaGetSymbolAddress((void**)&xW,    g_xW);
    cudaGetSymbolAddress((void**)&hW,    g_hW);
    cudaGetSymbolAddress((void**)&inp0,  g_inp0);
    cudaGetSymbolAddress((void**)&h,     g_h);
    cudaGetSymbolAddress((void**)&gates, g_gates);
    cudaGetSymbolAddress((void**)&bsum,  g_bsum);

    const long long ldO = (long long)T_ * V_;

    zero_state<<<96, 1024>>>();
    bias_sum<<<4, 1024>>>(bih[0], bhh[0], bih[1], bhh[1], bih[2], bhh[2]);

    // xW[b,s,:] = x @ W1x^T   (M=4096 via grid.y m-tiles)
    gemm32<64><<<dim3(H_ / 64, (B_ * S1_) / 32), 128>>>(
        x, E_, W1, E_ + H_, E_,
        nullptr, 0, nullptr, 0, 0,
        nullptr, xW, H_);

    for (int t = 0; t < T_; t++) {
        // hW = h2 @ W1h^T + b1
        gemm32<16><<<dim3(H_ / 16, 1), 128>>>(
            h + 2 * B_ * H_, H_, W1 + E_, E_ + H_, H_,
            nullptr, 0, nullptr, 0, 0,
            b1, hW, H_);

        attn_scores<<<dim3(S1_, B_), 128>>>(W2, b2);
        attn_context<<<dim3(E_ / 128, B_), 128>>>(x, tseq, emb, t);

        // layer 0: gates = inp0 @ Wih0^T + h0 @ Whh0^T + bsum0
        gemm32<32><<<dim3(4 * H_ / 32, 1), 128>>>(
            inp0, 2 * E_, Wih[0], 2 * E_, 2 * E_,
            h, H_, Whh[0], H_, H_,
            bsum, gates, 4 * H_);
        lstm_pointwise<<<B_, 1024>>>(0);

        // layer 1
        gemm32<32><<<dim3(4 * H_ / 32, 1), 128>>>(
            h, H_, Wih[1], H_, H_,
            h + B_ * H_, H_, Whh[1], H_, H_,
            bsum + 4 * H_, gates, 4 * H_);
        lstm_pointwise<<<B_, 1024>>>(1);

        // layer 2
        gemm32<32><<<dim3(4 * H_ / 32, 1), 128>>>(
            h + B_ * H_, H_, Wih[2], H_, H_,
            h + 2 * B_ * H_, H_, Whh[2], H_, H_,
            bsum + 8 * H_, gates, 4 * H_);
        lstm_pointwise<<<B_, 1024>>>(2);

        // logits -> d_out[:, t, :], then in-place log_softmax
        gemm32<64><<<dim3(V_ / 64, 1), 128>>>(
            h + 2 * B_ * H_, H_, fcW, H_, H_,
            nullptr, 0, nullptr, 0, 0,
            fcb, out + (size_t)t * V_, ldO);
        logsoftmax_v<<<B_, 1024>>>(out + (size_t)t * V_, ldO);
    }
}

// round 9
// speedup vs baseline: 3.1407x; 3.1407x over previous
#include <cuda_runtime.h>
#include <math.h>
#include <stdint.h>

#define B_  32
#define S1_ 128
#define T_  50
#define E_  768
#define H_  1024
#define V_  32000

// ---------------- device scratch (no allocation allowed) ----------------
__device__ float g_xW[B_ * S1_ * H_];     // x @ W1x^T  (precomputed once)
__device__ float g_hW[B_ * H_];           // reduced h2 @ W1h^T + b1 (per step)
__device__ float g_scores[B_ * S1_];
__device__ float g_inp0[B_ * 2 * E_];     // [emb_t ; context]
__device__ float g_h[3 * B_ * H_];
__device__ float g_c[3 * B_ * H_];
__device__ float g_bsum[3 * 4 * H_];      // bih + bhh per layer
__device__ float g_part[8 * B_ * 4 * H_]; // split-K partials (max 8 x 32 x 4096)

// ---------------- f32x2 packed helpers ----------------
__device__ __forceinline__ unsigned long long ffma2_(unsigned long long a,
                                                     unsigned long long b,
                                                     unsigned long long c) {
    unsigned long long d;
    asm("fma.rn.f32x2 %0, %1, %2, %3;" : "=l"(d) : "l"(a), "l"(b), "l"(c));
    return d;
}
__device__ __forceinline__ unsigned long long bcast2_(float x) {
    unsigned long long r;
    asm("mov.b64 %0, {%1, %1};" : "=l"(r) : "f"(x));
    return r;
}
__device__ __forceinline__ void unpack2_(unsigned long long v, float& lo, float& hi) {
    asm("mov.b64 {%0, %1}, %2;" : "=f"(lo), "=f"(hi) : "l"(v));
}
// TF32 operand rounding (matches cublas TF32 path: cvt.rna)
__device__ __forceinline__ float tf32r(float x) {
    unsigned u;
    asm("cvt.rna.tf32.f32 %0, %1;" : "=r"(u) : "f"(x));
    return __uint_as_float(u);
}

// ---------------- GEMM: out[m,n] = sum_k tf32(A[m,k]) * tf32(W[n,k])
// M=32 per m-tile (blockIdx.z). 64 columns per block (blockIdx.x).
// Split-K: blockIdx.y picks a K-slice of length Kslice; partial results go to
// g_part[(ksOff + by)*32*N ...] when !FINAL; FINAL writes out(+bias) directly.
// 128 threads: ng = tid&31 -> columns n0=2*ng, n0+1; mg = tid>>5 -> rows 8*mg..+7.
// Pipeline: LDG next chunk into regs while computing current chunk from smem.
template <bool FINAL>
__global__ void __launch_bounds__(128) gemmk(
    const float* __restrict__ A, int ldA,
    const float* __restrict__ W, int ldW,
    int Kslice,
    const float* __restrict__ bias,
    float* __restrict__ out, long long ldOut,
    float* __restrict__ partial, int N, int ksOff)
{
    __shared__ __align__(16) float shA[32 * 36];   // [kk][m] padded
    __shared__ __align__(16) float shW[32 * 66];   // [kk][n] stride 66

    const int tid   = threadIdx.x;
    const int ng    = tid & 31;
    const int mg    = tid >> 5;
    const int m0    = mg * 8;
    const int nbase = blockIdx.x * 64;
    const int mrow0 = blockIdx.z * 32;
    const int kbase = blockIdx.y * Kslice;
    const int NC    = Kslice >> 5;

    unsigned long long acc0[4], acc1[4];
#pragma unroll
    for (int r = 0; r < 4; r++) { acc0[r] = 0ull; acc1[r] = 0ull; }

    float4 aR[2], wR[4];

    // chunk loaders (global -> regs)
    auto loadChunk = [&](int c) {
        const int k0 = kbase + c * 32;
#pragma unroll
        for (int j = 0; j < 2; j++) {
            const int f4 = tid + j * 128;
            const int m  = f4 >> 3, kq = f4 & 7;
            aR[j] = *reinterpret_cast<const float4*>(
                &A[(size_t)(mrow0 + m) * ldA + k0 + kq * 4]);
        }
#pragma unroll
        for (int j = 0; j < 4; j++) {
            const int f4 = tid + j * 128;
            const int r  = f4 >> 3, kq = f4 & 7;
            wR[j] = *reinterpret_cast<const float4*>(
                &W[(size_t)(nbase + r) * ldW + kbase + c * 32 + kq * 4]);
        }
    };

    loadChunk(0);

    for (int c = 0; c < NC; c++) {
        __syncthreads();   // smem free from previous compute
        // store staged regs to smem (with TF32 rounding)
#pragma unroll
        for (int j = 0; j < 2; j++) {
            const int f4 = tid + j * 128;
            const int m  = f4 >> 3, kq = f4 & 7;
            shA[(kq * 4 + 0) * 36 + m] = tf32r(aR[j].x);
            shA[(kq * 4 + 1) * 36 + m] = tf32r(aR[j].y);
            shA[(kq * 4 + 2) * 36 + m] = tf32r(aR[j].z);
            shA[(kq * 4 + 3) * 36 + m] = tf32r(aR[j].w);
        }
#pragma unroll
        for (int j = 0; j < 4; j++) {
            const int f4 = tid + j * 128;
            const int r  = f4 >> 3, kq = f4 & 7;
            shW[(kq * 4 + 0) * 66 + r] = tf32r(wR[j].x);
            shW[(kq * 4 + 1) * 66 + r] = tf32r(wR[j].y);
            shW[(kq * 4 + 2) * 66 + r] = tf32r(wR[j].z);
            shW[(kq * 4 + 3) * 66 + r] = tf32r(wR[j].w);
        }
        __syncthreads();
        if (c + 1 < NC) loadChunk(c + 1);   // overlap with compute

#pragma unroll
        for (int kk = 0; kk < 32; kk++) {
            const ulonglong2 a01 = *reinterpret_cast<const ulonglong2*>(&shA[kk * 36 + m0]);
            const ulonglong2 a23 = *reinterpret_cast<const ulonglong2*>(&shA[kk * 36 + m0 + 4]);
            const float2 wv = *reinterpret_cast<const float2*>(&shW[kk * 66 + 2 * ng]);
            const unsigned long long w0 = bcast2_(wv.x);
            const unsigned long long w1 = bcast2_(wv.y);
            acc0[0] = ffma2_(a01.x, w0, acc0[0]);
            acc0[1] = ffma2_(a01.y, w0, acc0[1]);
            acc0[2] = ffma2_(a23.x, w0, acc0[2]);
            acc0[3] = ffma2_(a23.y, w0, acc0[3]);
            acc1[0] = ffma2_(a01.x, w1, acc1[0]);
            acc1[1] = ffma2_(a01.y, w1, acc1[1]);
            acc1[2] = ffma2_(a23.x, w1, acc1[2]);
            acc1[3] = ffma2_(a23.y, w1, acc1[3]);
        }
    }

    const int n0 = nbase + 2 * ng;
    if (FINAL) {
        const float bv0 = bias ? bias[n0] : 0.f;
        const float bv1 = bias ? bias[n0 + 1] : 0.f;
#pragma unroll
        for (int r = 0; r < 4; r++) {
            float lo, hi;
            const int m = mrow0 + m0 + 2 * r;
            unpack2_(acc0[r], lo, hi);
            out[(size_t)m * ldOut + n0]           = lo + bv0;
            out[(size_t)(m + 1) * ldOut + n0]     = hi + bv0;
            unpack2_(acc1[r], lo, hi);
            out[(size_t)m * ldOut + n0 + 1]       = lo + bv1;
            out[(size_t)(m + 1) * ldOut + n0 + 1] = hi + bv1;
        }
    } else {
        float* p = partial + (size_t)(ksOff + blockIdx.y) * 32 * N;
#pragma unroll
        for (int r = 0; r < 4; r++) {
            float lo, hi;
            const int m = m0 + 2 * r;
            unpack2_(acc0[r], lo, hi);
            p[(size_t)m * N + n0]           = lo;
            p[(size_t)(m + 1) * N + n0]     = hi;
            unpack2_(acc1[r], lo, hi);
            p[(size_t)m * N + n0 + 1]       = lo;
            p[(size_t)(m + 1) * N + n0 + 1] = hi;
        }
    }
}

// ---------------- reduce hW partials (+b1) ----------------
__global__ void __launch_bounds__(1024) hw_reduce(const float* __restrict__ b1)
{
    const int b = blockIdx.x, h = threadIdx.x;
    float v = b1[h];
#pragma unroll
    for (int ks = 0; ks < 8; ks++)
        v += g_part[(size_t)(ks * 32 + b) * 1024 + h];
    g_hW[b * H_ + h] = v;
}

// ---------------- attention: scores[b,s] = sum_h relu(xW + hW) * w2 + b2 ----------------
__global__ void __launch_bounds__(128) attn_scores(const float* __restrict__ w2,
                                                   const float* __restrict__ b2p)
{
    const int s = blockIdx.x, b = blockIdx.y, tid = threadIdx.x;
    const float* xw = g_xW + (size_t)(b * S1_ + s) * H_;
    const float* hw = g_hW + b * H_;
    float p = 0.f;
#pragma unroll 4
    for (int h = tid; h < H_; h += 128) {
        float v = xw[h] + hw[h];          // b1 already folded into hW
        v = fmaxf(v, 0.f);
        p += v * w2[h];
    }
    __shared__ float red[128];
    red[tid] = p; __syncthreads();
    for (int st = 64; st > 0; st >>= 1) {
        if (tid < st) red[tid] += red[tid + st];
        __syncthreads();
    }
    if (tid == 0) g_scores[b * S1_ + s] = red[0] + b2p[0];
}

// ---------------- attention: log_softmax(scores) -> context; also build inp0 ----------------
__global__ void __launch_bounds__(512) attn_context(const float* __restrict__ x,
                                                    const int* __restrict__ tseq,
                                                    const float* __restrict__ emb,
                                                    int t)
{
    const int c = blockIdx.x, b = blockIdx.y, tid = threadIdx.x;
    const int et = tid & 127, sq = tid >> 7;
    __shared__ float sc[128];
    __shared__ float red[128];
    __shared__ float acc[4 * 128];

    if (tid < 128) red[tid] = g_scores[b * S1_ + tid];
    __syncthreads();
    for (int st = 64; st > 0; st >>= 1) {
        if (tid < st) red[tid] = fmaxf(red[tid], red[tid + st]);
        __syncthreads();
    }
    const float mx = red[0];
    __syncthreads();
    if (tid < 128) {
        sc[tid]  = g_scores[b * S1_ + tid] - mx;
        red[tid] = expf(sc[tid]);
    }
    __syncthreads();
    for (int st = 64; st > 0; st >>= 1) {
        if (tid < st) red[tid] += red[tid + st];
        __syncthreads();
    }
    const float lse = logf(red[0]);
    __syncthreads();
    if (tid < 128) sc[tid] -= lse;        // logw
    __syncthreads();

    const int e = c * 128 + et;           // e in [0,768)
    const float* xb = x + ((size_t)b * S1_ + sq * 32) * E_ + e;
    float ctx = 0.f;
#pragma unroll 8
    for (int s = 0; s < 32; s++) ctx += sc[sq * 32 + s] * xb[(size_t)s * E_];
    acc[sq * 128 + et] = ctx;
    __syncthreads();
    if (tid < 128) {
        const float v = acc[tid] + acc[128 + tid] + acc[256 + tid] + acc[384 + tid];
        const int ee = c * 128 + tid;
        g_inp0[b * 2 * E_ + E_ + ee] = v;
        const int tgt = tseq[b * T_ + t];
        g_inp0[b * 2 * E_ + ee] = emb[(size_t)tgt * E_ + ee];
    }
}

// ---------------- LSTM pointwise: reduce 8 gate partials + biases + activations ----------------
__global__ void __launch_bounds__(1024) lstm_pointwise(int l)
{
    const int b = blockIdx.x, j = threadIdx.x;
    float gi = g_bsum[l * 4 * H_ + j];
    float gf = g_bsum[l * 4 * H_ + H_ + j];
    float gg = g_bsum[l * 4 * H_ + 2 * H_ + j];
    float go = g_bsum[l * 4 * H_ + 3 * H_ + j];
#pragma unroll
    for (int ks = 0; ks < 8; ks++) {
        const float* p = g_part + (size_t)(ks * 32 + b) * 4 * H_;
        gi += p[j];
        gf += p[H_ + j];
        gg += p[2 * H_ + j];
        go += p[3 * H_ + j];
    }
    float* cp = g_c + (size_t)(l * B_ + b) * H_ + j;
    float* hp = g_h + (size_t)(l * B_ + b) * H_ + j;
    const float si = 1.f / (1.f + expf(-gi));
    const float sf = 1.f / (1.f + expf(-gf));
    const float so = 1.f / (1.f + expf(-go));
    const float cn = sf * (*cp) + si * tanhf(gg);
    *cp = cn;
    *hp = so * tanhf(cn);
}

// ---------------- in-place log_softmax over V per batch row (float4) ----------------
__global__ void __launch_bounds__(1024) logsoftmax_v(float* __restrict__ out, long long ldOut)
{
    const int b = blockIdx.x, tid = threadIdx.x;
    float4* row = reinterpret_cast<float4*>(out + (size_t)b * ldOut);
    const int NV4 = V_ / 4;               // 8000
    __shared__ float red[1024];

    float m = -1e30f;
    for (int v = tid; v < NV4; v += 1024) {
        const float4 r4 = row[v];
        m = fmaxf(m, fmaxf(fmaxf(r4.x, r4.y), fmaxf(r4.z, r4.w)));
    }
    red[tid] = m; __syncthreads();
    for (int st = 512; st > 0; st >>= 1) {
        if (tid < st) red[tid] = fmaxf(red[tid], red[tid + st]);
        __syncthreads();
    }
    m = red[0];
    __syncthreads();

    float s = 0.f;
    for (int v = tid; v < NV4; v += 1024) {
        const float4 r4 = row[v];
        s += expf(r4.x - m) + expf(r4.y - m) + expf(r4.z - m) + expf(r4.w - m);
    }
    red[tid] = s; __syncthreads();
    for (int st = 512; st > 0; st >>= 1) {
        if (tid < st) red[tid] += red[tid + st];
        __syncthreads();
    }
    const float lse = logf(red[0]);

    for (int v = tid; v < NV4; v += 1024) {
        float4 r4 = row[v];
        r4.x = (r4.x - m) - lse;
        r4.y = (r4.y - m) - lse;
        r4.z = (r4.z - m) - lse;
        r4.w = (r4.w - m) - lse;
        row[v] = r4;
    }
}

// ---------------- init kernels ----------------
__global__ void zero_state()
{
    const int idx = blockIdx.x * 1024 + threadIdx.x;
    if (idx < 3 * B_ * H_) { g_h[idx] = 0.f; g_c[idx] = 0.f; }
}
__global__ void bias_sum(const float* bi0, const float* bh0,
                         const float* bi1, const float* bh1,
                         const float* bi2, const float* bh2)
{
    const int i = blockIdx.x * 1024 + threadIdx.x;
    if (i < 4 * H_) {
        g_bsum[i]            = bi0[i] + bh0[i];
        g_bsum[4 * H_ + i]   = bi1[i] + bh1[i];
        g_bsum[8 * H_ + i]   = bi2[i] + bh2[i];
    }
}

// ---------------- launch ----------------
extern "C" void kernel_launch(void* const* d_in, const int* in_sizes, int n_in,
                              void* d_out, int out_size)
{
    const float* x    = (const float*)d_in[0];
    const int*   tseq = (const int*)  d_in[1];
    const float* emb  = (const float*)d_in[2];
    const float* W1   = (const float*)d_in[3];   // (H, E+H)
    const float* b1   = (const float*)d_in[4];
    const float* W2   = (const float*)d_in[5];   // (1, H)
    const float* b2   = (const float*)d_in[6];

    // Input ordering: setup_inputs() dict order puts fc_W, fc_b at [7],[8].
    const float *fcW, *fcb;
    const float *Wih[3], *Whh[3], *bih[3], *bhh[3];
    int base;
    if (in_sizes[7] == V_ * H_) {          // dict order (expected)
        fcW = (const float*)d_in[7];
        fcb = (const float*)d_in[8];
        base = 9;
    } else {                                // signature order (fallback)
        fcW = (const float*)d_in[19];
        fcb = (const float*)d_in[20];
        base = 7;
    }
    for (int l = 0; l < 3; l++) {
        Wih[l] = (const float*)d_in[base + 4 * l + 0];
        Whh[l] = (const float*)d_in[base + 4 * l + 1];
        bih[l] = (const float*)d_in[base + 4 * l + 2];
        bhh[l] = (const float*)d_in[base + 4 * l + 3];
    }
    float* out = (float*)d_out;

    float *xW, *inp0, *h, *part;
    cudaGetSymbolAddress((void**)&xW,   g_xW);
    cudaGetSymbolAddress((void**)&inp0, g_inp0);
    cudaGetSymbolAddress((void**)&h,    g_h);
    cudaGetSymbolAddress((void**)&part, g_part);

    const long long ldO = (long long)T_ * V_;

    zero_state<<<96, 1024>>>();
    bias_sum<<<4, 1024>>>(bih[0], bhh[0], bih[1], bhh[1], bih[2], bhh[2]);

    // xW[b,s,:] = x @ W1x^T   (4096 rows via blockIdx.z m-tiles)
    gemmk<true><<<dim3(H_ / 64, 1, (B_ * S1_) / 32), 128>>>(
        x, E_, W1, E_ + H_, E_, nullptr, xW, H_, nullptr, H_, 0);

    for (int t = 0; t < T_; t++) {
        // hW partials: h2 @ W1h^T  (split-K 8)
        gemmk<false><<<dim3(H_ / 64, 8, 1), 128>>>(
            h + 2 * B_ * H_, H_, W1 + E_, E_ + H_, H_ / 8,
            nullptr, nullptr, 0, part, H_, 0);
        hw_reduce<<<B_, 1024>>>(b1);

        attn_scores<<<dim3(S1_, B_), 128>>>(W2, b2);
        attn_context<<<dim3(E_ / 128, B_), 512>>>(x, tseq, emb, t);

        // layer 0: gates partials = inp0 @ Wih0^T (slices 0-3) + h0 @ Whh0^T (slices 4-7)
        gemmk<false><<<dim3(4 * H_ / 64, 4, 1), 128>>>(
            inp0, 2 * E_, Wih[0], 2 * E_, (2 * E_) / 4,
            nullptr, nullptr, 0, part, 4 * H_, 0);
        gemmk<false><<<dim3(4 * H_ / 64, 4, 1), 128>>>(
            h, H_, Whh[0], H_, H_ / 4,
            nullptr, nullptr, 0, part, 4 * H_, 4);
        lstm_pointwise<<<B_, 1024>>>(0);

        // layer 1
        gemmk<false><<<dim3(4 * H_ / 64, 4, 1), 128>>>(
            h, H_, Wih[1], H_, H_ / 4,
            nullptr, nullptr, 0, part, 4 * H_, 0);
        gemmk<false><<<dim3(4 * H_ / 64, 4, 1), 128>>>(
            h + B_ * H_, H_, Whh[1], H_, H_ / 4,
            nullptr, nullptr, 0, part, 4 * H_, 4);
        lstm_pointwise<<<B_, 1024>>>(1);

        // layer 2
        gemmk<false><<<dim3(4 * H_ / 64, 4, 1), 128>>>(
            h + B_ * H_, H_, Wih[2], H_, H_ / 4,
            nullptr, nullptr, 0, part, 4 * H_, 0);
        gemmk<false><<<dim3(4 * H_ / 64, 4, 1), 128>>>(
            h + 2 * B_ * H_, H_, Whh[2], H_, H_ / 4,
            nullptr, nullptr, 0, part, 4 * H_, 4);
        lstm_pointwise<<<B_, 1024>>>(2);

        // logits -> d_out[:, t, :], then in-place log_softmax
        gemmk<true><<<dim3(V_ / 64, 1, 1), 128>>>(
            h + 2 * B_ * H_, H_, fcW, H_, H_,
            fcb, out + (size_t)t * V_, ldO, nullptr, V_, 0);
        logsoftmax_v<<<B_, 1024>>>(out + (size_t)t * V_, ldO);
    }
}

// round 11
// speedup vs baseline: 3.5497x; 1.1302x over previous
#include <cuda_runtime.h>
#include <math.h>
#include <stdint.h>

#define B_  32
#define S1_ 128
#define T_  50
#define E_  768
#define H_  1024
#define V_  32000

// ---------------- device scratch (no allocation allowed) ----------------
__device__ float g_xW[B_ * S1_ * H_];      // x @ W1x^T (precomputed once)
__device__ float g_inp0[B_ * 2 * E_];      // [emb_t ; context]
__device__ float g_h[3 * B_ * H_];
__device__ float g_c[3 * B_ * H_];
__device__ float g_bsum[3 * 4 * H_];       // bih + bhh per layer
__device__ float g_part[16 * B_ * 4 * H_]; // split-K partials (16 x 32 x 4096)
__device__ float g_fcpart[4 * B_ * V_];    // fc split-K partials (4 x 32 x 32000)

// ---------------- f32x2 packed helpers ----------------
__device__ __forceinline__ unsigned long long ffma2_(unsigned long long a,
                                                     unsigned long long b,
                                                     unsigned long long c) {
    unsigned long long d;
    asm("fma.rn.f32x2 %0, %1, %2, %3;" : "=l"(d) : "l"(a), "l"(b), "l"(c));
    return d;
}
__device__ __forceinline__ unsigned long long bcast2_(float x) {
    unsigned long long r;
    asm("mov.b64 %0, {%1, %1};" : "=l"(r) : "f"(x));
    return r;
}
__device__ __forceinline__ void unpack2_(unsigned long long v, float& lo, float& hi) {
    asm("mov.b64 {%0, %1}, %2;" : "=f"(lo), "=f"(hi) : "l"(v));
}
// TF32 operand rounding (matches cublas TF32 path: cvt.rna)
__device__ __forceinline__ float tf32r(float x) {
    unsigned u;
    asm("cvt.rna.tf32.f32 %0, %1;" : "=r"(u) : "f"(x));
    return __uint_as_float(u);
}

// ---------------- shared GEMM core: 32 rows x 64 cols per block, 128 threads
// dst[m*Nout + nbase+2*ng(+1)] = sum over K-chunk [kbase, kbase+NC*32)
__device__ __forceinline__ void gemm_core32(
    const float* __restrict__ A, int ldA,
    const float* __restrict__ W, int ldW,
    int kbase, int NC, int nbase,
    float* __restrict__ dst, int Nout,
    float* shA, float* shW)
{
    const int tid = threadIdx.x;
    const int ng  = tid & 31;
    const int mg  = tid >> 5;
    const int m0  = mg * 8;

    unsigned long long acc0[4], acc1[4];
#pragma unroll
    for (int r = 0; r < 4; r++) { acc0[r] = 0ull; acc1[r] = 0ull; }

    float4 aR[2], wR[4];
    auto loadChunk = [&](int c) {
        const int k0 = kbase + c * 32;
#pragma unroll
        for (int j = 0; j < 2; j++) {
            const int f4 = tid + j * 128;
            const int m  = f4 >> 3, kq = f4 & 7;
            aR[j] = *reinterpret_cast<const float4*>(&A[(size_t)m * ldA + k0 + kq * 4]);
        }
#pragma unroll
        for (int j = 0; j < 4; j++) {
            const int f4 = tid + j * 128;
            const int r  = f4 >> 3, kq = f4 & 7;
            wR[j] = *reinterpret_cast<const float4*>(
                &W[(size_t)(nbase + r) * ldW + k0 + kq * 4]);
        }
    };

    loadChunk(0);
    for (int c = 0; c < NC; c++) {
        __syncthreads();
#pragma unroll
        for (int j = 0; j < 2; j++) {
            const int f4 = tid + j * 128;
            const int m  = f4 >> 3, kq = f4 & 7;
            shA[(kq * 4 + 0) * 36 + m] = tf32r(aR[j].x);
            shA[(kq * 4 + 1) * 36 + m] = tf32r(aR[j].y);
            shA[(kq * 4 + 2) * 36 + m] = tf32r(aR[j].z);
            shA[(kq * 4 + 3) * 36 + m] = tf32r(aR[j].w);
        }
#pragma unroll
        for (int j = 0; j < 4; j++) {
            const int f4 = tid + j * 128;
            const int r  = f4 >> 3, kq = f4 & 7;
            shW[(kq * 4 + 0) * 66 + r] = tf32r(wR[j].x);
            shW[(kq * 4 + 1) * 66 + r] = tf32r(wR[j].y);
            shW[(kq * 4 + 2) * 66 + r] = tf32r(wR[j].z);
            shW[(kq * 4 + 3) * 66 + r] = tf32r(wR[j].w);
        }
        __syncthreads();
        if (c + 1 < NC) loadChunk(c + 1);

#pragma unroll
        for (int kk = 0; kk < 32; kk++) {
            const ulonglong2 a01 = *reinterpret_cast<const ulonglong2*>(&shA[kk * 36 + m0]);
            const ulonglong2 a23 = *reinterpret_cast<const ulonglong2*>(&shA[kk * 36 + m0 + 4]);
            const float2 wv = *reinterpret_cast<const float2*>(&shW[kk * 66 + 2 * ng]);
            const unsigned long long w0 = bcast2_(wv.x);
            const unsigned long long w1 = bcast2_(wv.y);
            acc0[0] = ffma2_(a01.x, w0, acc0[0]);
            acc0[1] = ffma2_(a01.y, w0, acc0[1]);
            acc0[2] = ffma2_(a23.x, w0, acc0[2]);
            acc0[3] = ffma2_(a23.y, w0, acc0[3]);
            acc1[0] = ffma2_(a01.x, w1, acc1[0]);
            acc1[1] = ffma2_(a01.y, w1, acc1[1]);
            acc1[2] = ffma2_(a23.x, w1, acc1[2]);
            acc1[3] = ffma2_(a23.y, w1, acc1[3]);
        }
    }

    const int n0 = nbase + 2 * ng;
#pragma unroll
    for (int r = 0; r < 4; r++) {
        float lo, hi;
        const int m = m0 + 2 * r;
        unpack2_(acc0[r], lo, hi);
        dst[(size_t)m * Nout + n0]           = lo;
        dst[(size_t)(m + 1) * Nout + n0]     = hi;
        unpack2_(acc1[r], lo, hi);
        dst[(size_t)m * Nout + n0 + 1]       = lo;
        dst[(size_t)(m + 1) * Nout + n0 + 1] = hi;
    }
}

// ---------------- carrier: main split-K GEMM (two segments over blockIdx.y)
// plus piggybacked fc partial tiles (blockIdx.x >= mainBx).
__global__ void __launch_bounds__(128) carrier(
    const float* __restrict__ Ain, int ldAa, const float* __restrict__ WA, int ldWA,
    int KsA, int yA,
    const float* __restrict__ Bin, int ldBb, const float* __restrict__ WB, int ldWB,
    int KsB,
    int mainBx, int N,
    const float* __restrict__ fcA, const float* __restrict__ fcW,
    int fcBase, int fcCount)
{
    __shared__ __align__(16) float shA[32 * 36];
    __shared__ __align__(16) float shW[32 * 66];
    const int bx = blockIdx.x, by = blockIdx.y;

    if (bx < mainBx) {
        const float* A; int ldA; const float* W; int ldW; int Ks, kb;
        if (by < yA) { A = Ain; ldA = ldAa; W = WA; ldW = ldWA; Ks = KsA; kb = by * KsA; }
        else         { A = Bin; ldA = ldBb; W = WB; ldW = ldWB; Ks = KsB; kb = (by - yA) * KsB; }
        gemm_core32(A, ldA, W, ldW, kb, Ks >> 5, bx * 64,
                    g_part + (size_t)by * 32 * N, N, shA, shW);
    } else {
        const int local = (bx - mainBx) * gridDim.y + by;
        if (local >= fcCount) return;
        const int flat  = fcBase + local;
        const int slice = flat / 500;
        const int tile  = flat - slice * 500;
        gemm_core32(fcA, H_, fcW, H_, slice * 256, 8, tile * 64,
                    g_fcpart + (size_t)slice * B_ * V_, V_, shA, shW);
    }
}

// ---------------- xW precompute: g_xW = x @ W1x^T (4096 rows via blockIdx.z)
__global__ void __launch_bounds__(128) gemm_xw(const float* __restrict__ x,
                                               const float* __restrict__ W1)
{
    __shared__ __align__(16) float shA[32 * 36];
    __shared__ __align__(16) float shW[32 * 66];
    const int z = blockIdx.z;
    gemm_core32(x + (size_t)z * 32 * E_, E_, W1, E_ + H_, 0, E_ / 32, blockIdx.x * 64,
                g_xW + (size_t)z * 32 * H_, H_, shA, shW);
}

// ---------------- fused attention: hW reduce(+b1) -> scores -> log_softmax -> context
__global__ void __launch_bounds__(1024) attn_all(
    const float* __restrict__ x, const int* __restrict__ tseq,
    const float* __restrict__ emb, const float* __restrict__ w2,
    const float* __restrict__ b2p, const float* __restrict__ b1, int t)
{
    const int b = blockIdx.x, tid = threadIdx.x;
    __shared__ float hw[H_];
    __shared__ float w2s[H_];
    __shared__ float sc[S1_];
    __shared__ float red4[4];

    {   // hW = b1 + sum of 16 partials (N=1024 layout in g_part)
        float v = b1[tid];
#pragma unroll
        for (int ks = 0; ks < 16; ks++)
            v += g_part[(size_t)(ks * 32 + b) * H_ + tid];
        hw[tid]  = v;
        w2s[tid] = w2[tid];
    }
    __syncthreads();

    const int lane = tid & 31, w = tid >> 5;
#pragma unroll
    for (int r = 0; r < 4; r++) {
        const int s = r * 32 + w;
        const float* xw = g_xW + ((size_t)b * S1_ + s) * H_;
        float p = 0.f;
#pragma unroll 8
        for (int i = 0; i < 32; i++) {
            const int hh = i * 32 + lane;
            float v = xw[hh] + hw[hh];
            v = fmaxf(v, 0.f);
            p += v * w2s[hh];
        }
#pragma unroll
        for (int o = 16; o > 0; o >>= 1) p += __shfl_xor_sync(0xffffffffu, p, o);
        if (lane == 0) sc[s] = p + b2p[0];
    }
    __syncthreads();

    // log_softmax over 128 scores
    if (tid < 128) {
        float v = sc[tid];
#pragma unroll
        for (int o = 16; o > 0; o >>= 1) v = fmaxf(v, __shfl_xor_sync(0xffffffffu, v, o));
        if (lane == 0) red4[w] = v;
    }
    __syncthreads();
    const float mx = fmaxf(fmaxf(red4[0], red4[1]), fmaxf(red4[2], red4[3]));
    __syncthreads();
    if (tid < 128) {
        const float sh = sc[tid] - mx;
        sc[tid] = sh;
        float e = expf(sh);
#pragma unroll
        for (int o = 16; o > 0; o >>= 1) e += __shfl_xor_sync(0xffffffffu, e, o);
        if (lane == 0) red4[w] = e;
    }
    __syncthreads();
    const float lse = logf(red4[0] + red4[1] + red4[2] + red4[3]);
    __syncthreads();
    if (tid < 128) sc[tid] -= lse;       // logw
    __syncthreads();

    // context + emb gather -> inp0
    if (tid < E_) {
        const float* xb = x + (size_t)b * S1_ * E_ + tid;
        float ctx = 0.f;
#pragma unroll 8
        for (int s = 0; s < S1_; s++) ctx += sc[s] * xb[(size_t)s * E_];
        g_inp0[b * 2 * E_ + E_ + tid] = ctx;
        const int tgt = tseq[b * T_ + t];
        g_inp0[b * 2 * E_ + tid] = emb[(size_t)tgt * E_ + tid];
    }
}

// ---------------- LSTM pointwise update (16 partials + biases) ----------------
__device__ __forceinline__ void lstm_update(int l, int b)
{
    const int j = threadIdx.x;
    float gi = g_bsum[l * 4 * H_ + j];
    float gf = g_bsum[l * 4 * H_ + H_ + j];
    float gg = g_bsum[l * 4 * H_ + 2 * H_ + j];
    float go = g_bsum[l * 4 * H_ + 3 * H_ + j];
#pragma unroll
    for (int ks = 0; ks < 16; ks++) {
        const float* p = g_part + (size_t)(ks * 32 + b) * 4 * H_;
        gi += p[j];
        gf += p[H_ + j];
        gg += p[2 * H_ + j];
        go += p[3 * H_ + j];
    }
    float* cp = g_c + (size_t)(l * B_ + b) * H_ + j;
    float* hp = g_h + (size_t)(l * B_ + b) * H_ + j;
    const float si = 1.f / (1.f + expf(-gi));
    const float sf = 1.f / (1.f + expf(-gf));
    const float so = 1.f / (1.f + expf(-go));
    const float cn = sf * (*cp) + si * tanhf(gg);
    *cp = cn;
    *hp = so * tanhf(cn);
}

__global__ void __launch_bounds__(1024) lstm_pw(int l) { lstm_update(l, blockIdx.x); }

// ---------------- logits from fc partials + log_softmax (one batch row) ------
__device__ __forceinline__ void logsoftmax_row(float* __restrict__ rowBase,
                                               const float* __restrict__ fcb, int b)
{
    float* row = rowBase + (size_t)b * ((long long)T_ * V_);
    const int tid = threadIdx.x;
    const int NV4 = V_ / 4;
    const float4* bb = (const float4*)fcb;
    const float4* p0 = (const float4*)(g_fcpart + (size_t)b * V_);
    const float4* p1 = (const float4*)(g_fcpart + (size_t)(B_ + b) * V_);
    const float4* p2 = (const float4*)(g_fcpart + (size_t)(2 * B_ + b) * V_);
    const float4* p3 = (const float4*)(g_fcpart + (size_t)(3 * B_ + b) * V_);
    float4* r4 = (float4*)row;
    __shared__ float red[1024];

    float m = -1e30f;
    for (int v = tid; v < NV4; v += 1024) {
        const float4 a = bb[v], q0 = p0[v], q1 = p1[v], q2 = p2[v], q3 = p3[v];
        float4 r;
        r.x = a.x + q0.x + q1.x + q2.x + q3.x;
        r.y = a.y + q0.y + q1.y + q2.y + q3.y;
        r.z = a.z + q0.z + q1.z + q2.z + q3.z;
        r.w = a.w + q0.w + q1.w + q2.w + q3.w;
        r4[v] = r;
        m = fmaxf(m, fmaxf(fmaxf(r.x, r.y), fmaxf(r.z, r.w)));
    }
    red[tid] = m; __syncthreads();
    for (int st = 512; st > 0; st >>= 1) {
        if (tid < st) red[tid] = fmaxf(red[tid], red[tid + st]);
        __syncthreads();
    }
    m = red[0];
    __syncthreads();

    float s = 0.f;
    for (int v = tid; v < NV4; v += 1024) {
        const float4 r = r4[v];
        s += expf(r.x - m) + expf(r.y - m) + expf(r.z - m) + expf(r.w - m);
    }
    red[tid] = s; __syncthreads();
    for (int st = 512; st > 0; st >>= 1) {
        if (tid < st) red[tid] += red[tid + st];
        __syncthreads();
    }
    const float lse = logf(red[0]);

    for (int v = tid; v < NV4; v += 1024) {
        float4 r = r4[v];
        r.x = (r.x - m) - lse;
        r.y = (r.y - m) - lse;
        r.z = (r.z - m) - lse;
        r.w = (r.w - m) - lse;
        r4[v] = r;
    }
}

// blocks 0..31: lp2(t); blocks 32..63: log_softmax for step t-1 (if any)
__global__ void __launch_bounds__(1024) lp2_ls(float* outPrevBase, const float* __restrict__ fcb)
{
    if (blockIdx.x < 32) {
        lstm_update(2, blockIdx.x);
    } else {
        if (!outPrevBase) return;
        logsoftmax_row(outPrevBase, fcb, blockIdx.x - 32);
    }
}

__global__ void __launch_bounds__(1024) ls_final(float* outBase, const float* __restrict__ fcb)
{
    logsoftmax_row(outBase, fcb, blockIdx.x);
}

// ---------------- init kernels ----------------
__global__ void zero_state()
{
    const int idx = blockIdx.x * 1024 + threadIdx.x;
    if (idx < 3 * B_ * H_) { g_h[idx] = 0.f; g_c[idx] = 0.f; }
}
__global__ void bias_sum(const float* bi0, const float* bh0,
                         const float* bi1, const float* bh1,
                         const float* bi2, const float* bh2)
{
    const int i = blockIdx.x * 1024 + threadIdx.x;
    if (i < 4 * H_) {
        g_bsum[i]          = bi0[i] + bh0[i];
        g_bsum[4 * H_ + i] = bi1[i] + bh1[i];
        g_bsum[8 * H_ + i] = bi2[i] + bh2[i];
    }
}

// ---------------- launch ----------------
extern "C" void kernel_launch(void* const* d_in, const int* in_sizes, int n_in,
                              void* d_out, int out_size)
{
    const float* x    = (const float*)d_in[0];
    const int*   tseq = (const int*)  d_in[1];
    const float* emb  = (const float*)d_in[2];
    const float* W1   = (const float*)d_in[3];   // (H, E+H)
    const float* b1   = (const float*)d_in[4];
    const float* W2   = (const float*)d_in[5];   // (1, H)
    const float* b2   = (const float*)d_in[6];

    const float *fcW, *fcb;
    const float *Wih[3], *Whh[3], *bih[3], *bhh[3];
    int base;
    if (in_sizes[7] == V_ * H_) {          // dict order (expected)
        fcW = (const float*)d_in[7];
        fcb = (const float*)d_in[8];
        base = 9;
    } else {                                // signature order (fallback)
        fcW = (const float*)d_in[19];
        fcb = (const float*)d_in[20];
        base = 7;
    }
    for (int l = 0; l < 3; l++) {
        Wih[l] = (const float*)d_in[base + 4 * l + 0];
        Whh[l] = (const float*)d_in[base + 4 * l + 1];
        bih[l] = (const float*)d_in[base + 4 * l + 2];
        bhh[l] = (const float*)d_in[base + 4 * l + 3];
    }
    float* out = (float*)d_out;

    float *inp0, *h;
    cudaGetSymbolAddress((void**)&inp0, g_inp0);
    cudaGetSymbolAddress((void**)&h,    g_h);
    float* h0 = h;
    float* h1 = h + B_ * H_;
    float* h2 = h + 2 * B_ * H_;

    zero_state<<<96, 1024>>>();
    bias_sum<<<4, 1024>>>(bih[0], bhh[0], bih[1], bhh[1], bih[2], bhh[2]);
    gemm_xw<<<dim3(16, 1, (B_ * S1_) / 32), 128>>>(x, W1);

    for (int t = 0; t < T_; t++) {
        const bool hasFc = (t > 0);
        const int  ex    = hasFc ? 32 : 0;   // extra x-blocks for 500 fc tiles
        const int  cnt   = hasFc ? 500 : 0;
        float* outPrev   = hasFc ? (out + (size_t)(t - 1) * V_) : nullptr;

        // hW partials (16 slices of K=64) + fc(t-1) slice group 0
        carrier<<<dim3(16 + ex, 16), 128>>>(
            h2, H_, W1 + E_, E_ + H_, 64, 16,
            nullptr, 0, nullptr, 0, 32,
            16, H_, h2, fcW, 0, cnt);

        attn_all<<<B_, 1024>>>(x, tseq, emb, W2, b2, b1, t);

        // layer 0 gates: segA inp0@Wih0 (8x192), segB h0@Whh0 (8x128) + fc grp 1
        carrier<<<dim3(64 + ex, 16), 128>>>(
            inp0, 2 * E_, Wih[0], 2 * E_, 192, 8,
            h0, H_, Whh[0], H_, 128,
            64, 4 * H_, h2, fcW, 500, cnt);
        lstm_pw<<<B_, 1024>>>(0);

        // layer 1 + fc grp 2
        carrier<<<dim3(64 + ex, 16), 128>>>(
            h0, H_, Wih[1], H_, 128, 8,
            h1, H_, Whh[1], H_, 128,
            64, 4 * H_, h2, fcW, 1000, cnt);
        lstm_pw<<<B_, 1024>>>(1);

        // layer 2 + fc grp 3
        carrier<<<dim3(64 + ex, 16), 128>>>(
            h1, H_, Wih[2], H_, 128, 8,
            h2, H_, Whh[2], H_, 128,
            64, 4 * H_, h2, fcW, 1500, cnt);

        // lp2(t) fused with log_softmax(t-1)
        lp2_ls<<<2 * B_, 1024>>>(outPrev, fcb);
    }

    // final step's fc + log_softmax
    carrier<<<dim3(125, 16), 128>>>(
        nullptr, 0, nullptr, 0, 32, 16,
        nullptr, 0, nullptr, 0, 32,
        0, H_, h2, fcW, 0, 2000);
    ls_final<<<B_, 1024>>>(out + (size_t)(T_ - 1) * V_, fcb);
}